// round 16
// baseline (speedup 1.0000x reference)
#include <cuda_runtime.h>
#include <cuda_bf16.h>
#include <stdint.h>

// Problem constants
#define BB 16
#define SS 1024
#define DD 1024
#define HH 16
#define DK 64
#define MTOK (BB*SS)          // 16384 token rows

// Scratch buffers (device globals — no allocation allowed)
__device__ float g_A[(size_t)MTOK * DD];
__device__ float g_B[(size_t)MTOK * DD];
__device__ float g_C[(size_t)MTOK * DD];
// 4 pairs of split-bf16 activation buffers (hi/lo), each MTOK*DD
__device__ __nv_bfloat16 g_bf[(size_t)4 * 2 * MTOK * DD];
// 6 weight pairs (hi/lo), each DD*DD, all stored [N,K]
__device__ __nv_bfloat16 g_w[(size_t)6 * 2 * DD * DD];

// ===========================================================================
// Helpers
// ===========================================================================
__device__ __forceinline__ uint32_t smem_u32(const void* p) {
    uint32_t a;
    asm("{ .reg .u64 t; cvta.to.shared.u64 t, %1; cvt.u32.u64 %0, t; }" : "=r"(a) : "l"(p));
    return a;
}

#define LDSM_X4(R0, R1, R2, R3, addr)                                          \
    asm volatile("ldmatrix.sync.aligned.m8n8.x4.shared.b16 {%0,%1,%2,%3}, [%4];" \
        : "=r"(R0), "=r"(R1), "=r"(R2), "=r"(R3) : "r"(addr))

__device__ __forceinline__ void mma16816(float* d, const uint32_t* a, const uint32_t* b) {
    asm volatile(
        "mma.sync.aligned.m16n8k16.row.col.f32.bf16.bf16.f32 "
        "{%0,%1,%2,%3}, {%4,%5,%6,%7}, {%8,%9}, {%0,%1,%2,%3};"
        : "+f"(d[0]), "+f"(d[1]), "+f"(d[2]), "+f"(d[3])
        : "r"(a[0]), "r"(a[1]), "r"(a[2]), "r"(a[3]), "r"(b[0]), "r"(b[1]));
}

__device__ __forceinline__ void split2(float a, float b, uint32_t& hi, uint32_t& lo) {
    __nv_bfloat16 ah = __float2bfloat16_rn(a);
    __nv_bfloat16 bh = __float2bfloat16_rn(b);
    __nv_bfloat16 al = __float2bfloat16_rn(a - __bfloat162float(ah));
    __nv_bfloat16 bl = __float2bfloat16_rn(b - __bfloat162float(bh));
    hi = (uint32_t)__bfloat16_as_ushort(ah) | ((uint32_t)__bfloat16_as_ushort(bh) << 16);
    lo = (uint32_t)__bfloat16_as_ushort(al) | ((uint32_t)__bfloat16_as_ushort(bl) << 16);
}

#define CP16(sm, gm) asm volatile("cp.async.cg.shared.global [%0], [%1], 16;" :: "r"(sm), "l"(gm))
#define CP_COMMIT()  asm volatile("cp.async.commit_group;")
#define CP_WAIT0()   asm volatile("cp.async.wait_group 0;" ::: "memory")
#define CP_WAIT1()   asm volatile("cp.async.wait_group 1;" ::: "memory")

// ===========================================================================
// Convert kernels (one-time per launch)
// ===========================================================================
__global__ void conv_a(const float* __restrict__ X,
                       __nv_bfloat16* __restrict__ Xh, __nv_bfloat16* __restrict__ Xl)
{
    const size_t i = ((size_t)blockIdx.x * 256 + threadIdx.x) * 4;
    const float4 v = *(const float4*)(X + i);
    uint32_t h0, l0, h1, l1;
    split2(v.x, v.y, h0, l0);
    split2(v.z, v.w, h1, l1);
    *(uint32_t*)(Xh + i)     = h0;  *(uint32_t*)(Xh + i + 2) = h1;
    *(uint32_t*)(Xl + i)     = l0;  *(uint32_t*)(Xl + i + 2) = l1;
}

// W [K,N] fp32 -> Wh/Wl [N,K] bf16 (transpose via smem)
__global__ void conv_w_t(const float* __restrict__ W,
                         __nv_bfloat16* __restrict__ Wh, __nv_bfloat16* __restrict__ Wl)
{
    __shared__ float t[32][33];
    const int n0 = blockIdx.x * 32;
    const int k0 = blockIdx.y * 32;
    const int tx = threadIdx.x, ty = threadIdx.y;
    #pragma unroll
    for (int j = ty; j < 32; j += 8)
        t[j][tx] = W[(size_t)(k0 + j) * DD + n0 + tx];
    __syncthreads();
    const int k = k0 + tx;
    #pragma unroll
    for (int j = ty; j < 32; j += 8) {
        const float v = t[tx][j];
        const __nv_bfloat16 hi = __float2bfloat16_rn(v);
        const __nv_bfloat16 lo = __float2bfloat16_rn(v - __bfloat162float(hi));
        Wh[(size_t)(n0 + j) * DD + k] = hi;
        Wl[(size_t)(n0 + j) * DD + k] = lo;
    }
}

// ===========================================================================
// Split-bf16 mma.sync GEMM: C = A[M,K] @ B^T, pre-split operands.
// CTA 256x128, 512 threads / 16 warps (4m x 4n), warp tile 64x32.
// BK=64, 2-stage cp.async ring, term-outer MMA order.
// Ops/MMA reduced 25% vs 128x128 (cp.async-issue relief).
// ===========================================================================
#define RSTRIDE 144                        // bytes per smem row (72 bf16)
#define A_BYTES (256 * RSTRIDE)            // 36864
#define B_BYTES (128 * RSTRIDE)            // 18432
#define STG_BYTES (2 * A_BYTES + 2 * B_BYTES)  // 110592
#define GEMM_SMEM (2 * STG_BYTES)          // 221184
#define NCHUNK (DD / 64)                   // 16

template<bool BIAS, bool RELU, bool OUTF32, bool OUTSPLIT>
__global__ void __launch_bounds__(512, 1) mma_gemm(
    const __nv_bfloat16* __restrict__ Ah, const __nv_bfloat16* __restrict__ Al,
    const __nv_bfloat16* __restrict__ Bh, const __nv_bfloat16* __restrict__ Bl,
    const float* __restrict__ bias,
    float* __restrict__ Cf,
    __nv_bfloat16* __restrict__ Ch, __nv_bfloat16* __restrict__ Cl)
{
    extern __shared__ char smem[];
    const uint32_t sbase = smem_u32(smem);
    const int tid  = threadIdx.x;
    const int lane = tid & 31;
    const int wid  = tid >> 5;           // 0..15
    const int wm   = wid & 3;            // 4 m-warps * 64 rows
    const int wn   = wid >> 2;           // 4 n-warps * 32 cols
    const int n0   = blockIdx.x * 128;
    const int m0   = blockIdx.y * 256;

    float acc[4][4][4] = {};             // [mt][n8][4]

    auto issue = [&](int c, int s) {
        const int k0 = c * 64;
        const uint32_t st = sbase + s * STG_BYTES;
        #pragma unroll
        for (int i = 0; i < 12; i++) {
            const int id = tid + 512 * i;              // 0..6143
            if (id < 4096) {                           // A: 2 tiles x 256 rows
                const int half = id >> 11;             // 0 Ah, 1 Al
                const int r    = (id >> 3) & 255;
                const int seg  = id & 7;
                const __nv_bfloat16* g = (half ? Al : Ah)
                    + (size_t)(m0 + r) * DD + k0 + seg * 8;
                CP16(st + half * A_BYTES + r * RSTRIDE + seg * 16, g);
            } else {                                   // B: 2 tiles x 128 rows
                const int id2  = id - 4096;
                const int half = id2 >> 10;            // 0 Bh, 1 Bl
                const int r    = (id2 >> 3) & 127;
                const int seg  = id2 & 7;
                const __nv_bfloat16* g = (half ? Bl : Bh)
                    + (size_t)(n0 + r) * DD + k0 + seg * 8;
                CP16(st + 2 * A_BYTES + half * B_BYTES + r * RSTRIDE + seg * 16, g);
            }
        }
    };

    const int arow   = lane & 15;
    const int acb    = ((lane >> 4) * 8) * 2;
    const int qq     = lane >> 3;
    const int lr     = lane & 7;
    const int brow_q = ((qq & 2) ? 8 : 0) + lr;
    const int bcb    = ((qq & 1) * 8) * 2;

    auto compute = [&](uint32_t stg) {
        const uint32_t sAh = stg;
        const uint32_t sAl = stg + A_BYTES;
        const uint32_t sBh = stg + 2 * A_BYTES;
        const uint32_t sBl = stg + 2 * A_BYTES + B_BYTES;
        #pragma unroll
        for (int ks = 0; ks < 4; ks++) {
            const int kb = ks * 32;
            uint32_t ah[4][4], al[4][4], bh[2][4], bl[2][4];
            #pragma unroll
            for (int mt = 0; mt < 4; mt++) {
                const uint32_t off = (uint32_t)((wm * 64 + mt * 16 + arow) * RSTRIDE + kb + acb);
                LDSM_X4(ah[mt][0], ah[mt][1], ah[mt][2], ah[mt][3], sAh + off);
                LDSM_X4(al[mt][0], al[mt][1], al[mt][2], al[mt][3], sAl + off);
            }
            #pragma unroll
            for (int p = 0; p < 2; p++) {
                const uint32_t off = (uint32_t)((wn * 32 + p * 16 + brow_q) * RSTRIDE + kb + bcb);
                LDSM_X4(bh[p][0], bh[p][1], bh[p][2], bh[p][3], sBh + off);
                LDSM_X4(bl[p][0], bl[p][1], bl[p][2], bl[p][3], sBl + off);
            }
            // term-outer: 16 independent accumulators back-to-back per term
            #pragma unroll
            for (int mt = 0; mt < 4; mt++)
                #pragma unroll
                for (int p = 0; p < 2; p++)
                    #pragma unroll
                    for (int h = 0; h < 2; h++)
                        mma16816(acc[mt][p * 2 + h], ah[mt], &bh[p][h * 2]);
            #pragma unroll
            for (int mt = 0; mt < 4; mt++)
                #pragma unroll
                for (int p = 0; p < 2; p++)
                    #pragma unroll
                    for (int h = 0; h < 2; h++)
                        mma16816(acc[mt][p * 2 + h], ah[mt], &bl[p][h * 2]);
            #pragma unroll
            for (int mt = 0; mt < 4; mt++)
                #pragma unroll
                for (int p = 0; p < 2; p++)
                    #pragma unroll
                    for (int h = 0; h < 2; h++)
                        mma16816(acc[mt][p * 2 + h], al[mt], &bh[p][h * 2]);
        }
    };

    // 2-stage ring: load(c+1) overlaps compute(c)
    issue(0, 0); CP_COMMIT();
    issue(1, 1); CP_COMMIT();
    for (int c = 0; c < NCHUNK; c++) {
        CP_WAIT1();            // chunk c arrived (c+1 may still be in flight)
        __syncthreads();
        compute(sbase + (c & 1) * STG_BYTES);
        if (c + 2 < NCHUNK) {
            __syncthreads();   // all warps done reading stage (c&1)
            issue(c + 2, c & 1);
        }
        CP_COMMIT();           // empty commit keeps group accounting exact
    }

    // Epilogue: warp tile 64x32 at (wm*64, wn*32)
    #pragma unroll
    for (int mt = 0; mt < 4; mt++) {
        const int row = m0 + wm * 64 + mt * 16 + (lane >> 2);
        #pragma unroll
        for (int nt = 0; nt < 4; nt++) {
            const int col = n0 + wn * 32 + nt * 8 + (lane & 3) * 2;
            float b0 = 0.f, b1 = 0.f;
            if (BIAS) { b0 = __ldg(bias + col); b1 = __ldg(bias + col + 1); }
            float2 v01, v23;
            v01.x = acc[mt][nt][0] + b0;  v01.y = acc[mt][nt][1] + b1;
            v23.x = acc[mt][nt][2] + b0;  v23.y = acc[mt][nt][3] + b1;
            if (RELU) {
                v01.x = fmaxf(v01.x, 0.f); v01.y = fmaxf(v01.y, 0.f);
                v23.x = fmaxf(v23.x, 0.f); v23.y = fmaxf(v23.y, 0.f);
            }
            if (OUTF32) {
                *(float2*)(Cf + (size_t)row * DD + col)       = v01;
                *(float2*)(Cf + (size_t)(row + 8) * DD + col) = v23;
            }
            if (OUTSPLIT) {
                uint32_t h, l;
                split2(v01.x, v01.y, h, l);
                *(uint32_t*)(Ch + (size_t)row * DD + col) = h;
                *(uint32_t*)(Cl + (size_t)row * DD + col) = l;
                split2(v23.x, v23.y, h, l);
                *(uint32_t*)(Ch + (size_t)(row + 8) * DD + col) = h;
                *(uint32_t*)(Cl + (size_t)(row + 8) * DD + col) = l;
            }
        }
    }
}

// ===========================================================================
// Tensor-core flash attention, pre-split bf16 inputs, double-buffered K/V,
// Q fragments hoisted out of the kt loop, term-outer MMA order.
// (unchanged — verified)
// ===========================================================================
#define AST 72
#define QTILE_B (128 * AST * 2)            // 18432
#define KTILE_B (64 * AST * 2)             // 9216
#define KVSTG (4 * KTILE_B)                // 36864
#define ATT_SMEM (2 * QTILE_B + 2 * KVSTG) // 110592

__global__ void __launch_bounds__(256) attn_mma_kernel(
    const __nv_bfloat16* __restrict__ Qh_, const __nv_bfloat16* __restrict__ Ql_,
    const __nv_bfloat16* __restrict__ Kh_, const __nv_bfloat16* __restrict__ Kl_,
    const __nv_bfloat16* __restrict__ Vh_, const __nv_bfloat16* __restrict__ Vl_,
    const unsigned char* __restrict__ mask,
    __nv_bfloat16* __restrict__ Ch, __nv_bfloat16* __restrict__ Cl)
{
    extern __shared__ char sm[];
    const uint32_t sb = smem_u32(sm);
    const int tid  = threadIdx.x;
    const int lane = tid & 31;
    const int w    = tid >> 5;
    const int qt   = blockIdx.x;           // 0..7
    const int bh   = blockIdx.y;
    const int b    = bh >> 4;
    const int h    = bh & 15;

    const uint32_t uQh = sb;
    const uint32_t uQl = sb + QTILE_B;
    const uint32_t kvBase = sb + 2 * QTILE_B;

    const size_t base = (size_t)b * SS * DD + (size_t)h * DK;

    // ---- Q tile cp.async ----
    #pragma unroll
    for (int i = 0; i < 8; i++) {
        const int id   = tid + 256 * i;
        const int tile = id >> 10;
        const int r    = (id >> 3) & 127;
        const int seg  = id & 7;
        const __nv_bfloat16* g = (tile ? Ql_ : Qh_)
            + base + (size_t)(qt * 128 + r) * DD + seg * 8;
        CP16(sb + tile * QTILE_B + r * 144 + seg * 16, g);
    }
    CP_COMMIT();

    auto issueK = [&](int kt, int s) {
        const uint32_t st = kvBase + s * KVSTG;
        #pragma unroll
        for (int i = 0; i < 4; i++) {
            const int id   = tid + 256 * i;
            const int tile = id >> 9;          // 0 hi, 1 lo
            const int r    = (id >> 3) & 63;
            const int seg  = id & 7;
            const __nv_bfloat16* g = (tile ? Kl_ : Kh_)
                + base + (size_t)(kt * 64 + r) * DD + seg * 8;
            CP16(st + tile * KTILE_B + r * 144 + seg * 16, g);
        }
    };

    const int vrow = (tid & 31) * 2;
    const int dblk = tid >> 5;
    uint4 vh0, vh1, vl0, vl1;
    auto ldgV = [&](int kt) {
        const __nv_bfloat16* gh = Vh_ + base + (size_t)(kt * 64 + vrow) * DD + dblk * 8;
        const __nv_bfloat16* gl = Vl_ + base + (size_t)(kt * 64 + vrow) * DD + dblk * 8;
        vh0 = *(const uint4*)gh;  vh1 = *(const uint4*)(gh + DD);
        vl0 = *(const uint4*)gl;  vl1 = *(const uint4*)(gl + DD);
    };
    auto stsV = [&](int s) {
        const uint32_t st = kvBase + s * KVSTG;
        const uint16_t* h0p = (const uint16_t*)&vh0;
        const uint16_t* h1p = (const uint16_t*)&vh1;
        const uint16_t* l0p = (const uint16_t*)&vl0;
        const uint16_t* l1p = (const uint16_t*)&vl1;
        #pragma unroll
        for (int d = 0; d < 8; d++) {
            const uint32_t off = (uint32_t)((dblk * 8 + d) * 144 + vrow * 2);
            *(uint32_t*)(sm + (st - sb) + 2 * KTILE_B + off) =
                (uint32_t)h0p[d] | ((uint32_t)h1p[d] << 16);
            *(uint32_t*)(sm + (st - sb) + 3 * KTILE_B + off) =
                (uint32_t)l0p[d] | ((uint32_t)l1p[d] << 16);
        }
    };

    const int r0 = lane >> 2;
    unsigned char pm[2];
    pm[0] = mask[(size_t)b * SS + qt * 128 + w * 16 + r0];
    pm[1] = mask[(size_t)b * SS + qt * 128 + w * 16 + r0 + 8];

    float m_r[2] = {-1e30f, -1e30f};
    float l_r[2] = {0.f, 0.f};
    float acc_o[8][4] = {};

    const float NEGV  = -4294967295.0f;
    const float scale = 1.0f / 8.000001f;

    const int arow   = lane & 15;
    const int acb    = ((lane >> 4) * 8) * 2;
    const int qq     = lane >> 3;
    const int lr     = lane & 7;
    const int brow_q = ((qq & 2) ? 8 : 0) + lr;
    const int bcb    = ((qq & 1) * 8) * 2;

    // ---- prologue: K(0) + V(0) ----
    issueK(0, 0); CP_COMMIT();
    ldgV(0);
    CP_WAIT0();
    __syncthreads();       // Q, K0 visible
    stsV(0);

    // ---- hoist Q fragments (kt-invariant) ----
    uint32_t qfh[4][4], qfl[4][4];
    #pragma unroll
    for (int ks = 0; ks < 4; ks++) {
        const uint32_t off = (uint32_t)((w * 16 + arow) * 144 + ks * 32 + acb);
        LDSM_X4(qfh[ks][0], qfh[ks][1], qfh[ks][2], qfh[ks][3], uQh + off);
        LDSM_X4(qfl[ks][0], qfl[ks][1], qfl[ks][2], qfl[ks][3], uQl + off);
    }
    __syncthreads();       // V0 visible

    const int kmax = 2 * qt + 1;
    for (int kt = 0; kt <= kmax; kt++) {
        const int s = kt & 1;
        const uint32_t st = kvBase + s * KVSTG;
        const uint32_t uKh = st;
        const uint32_t uKl = st + KTILE_B;
        const uint32_t uVh = st + 2 * KTILE_B;
        const uint32_t uVl = st + 3 * KTILE_B;

        if (kt < kmax) {
            issueK(kt + 1, s ^ 1); CP_COMMIT();
            ldgV(kt + 1);
        }

        // ---- scores S = Q @ K^T (term-outer) ----
        float sc[8][4] = {};
        #pragma unroll
        for (int ks = 0; ks < 4; ks++) {
            const int kb = ks * 32;
            uint32_t kh[4][4], kl[4][4];
            #pragma unroll
            for (int p = 0; p < 4; p++) {
                const uint32_t off = (uint32_t)((p * 16 + brow_q) * 144 + kb + bcb);
                LDSM_X4(kh[p][0], kh[p][1], kh[p][2], kh[p][3], uKh + off);
                LDSM_X4(kl[p][0], kl[p][1], kl[p][2], kl[p][3], uKl + off);
            }
            #pragma unroll
            for (int p = 0; p < 4; p++)
                #pragma unroll
                for (int hh = 0; hh < 2; hh++)
                    mma16816(sc[p * 2 + hh], qfh[ks], &kh[p][hh * 2]);
            #pragma unroll
            for (int p = 0; p < 4; p++)
                #pragma unroll
                for (int hh = 0; hh < 2; hh++)
                    mma16816(sc[p * 2 + hh], qfh[ks], &kl[p][hh * 2]);
            #pragma unroll
            for (int p = 0; p < 4; p++)
                #pragma unroll
                for (int hh = 0; hh < 2; hh++)
                    mma16816(sc[p * 2 + hh], qfl[ks], &kh[p][hh * 2]);
        }

        // ---- scale + causal/pad mask ----
        const int qg0 = qt * 128 + w * 16 + r0;
        #pragma unroll
        for (int nt = 0; nt < 8; nt++) {
            const int cg = kt * 64 + nt * 8 + (lane & 3) * 2;
            #pragma unroll
            for (int j = 0; j < 4; j++) {
                const int row_g = (j >> 1) ? qg0 + 8 : qg0;
                const int col_g = cg + (j & 1);
                sc[nt][j] *= scale;
                if (col_g > row_g || pm[j >> 1]) sc[nt][j] = NEGV;
            }
        }

        // ---- online softmax ----
        #pragma unroll
        for (int half = 0; half < 2; half++) {
            float tm = -1e30f;
            #pragma unroll
            for (int nt = 0; nt < 8; nt++)
                tm = fmaxf(tm, fmaxf(sc[nt][half * 2], sc[nt][half * 2 + 1]));
            tm = fmaxf(tm, __shfl_xor_sync(0xffffffffu, tm, 1));
            tm = fmaxf(tm, __shfl_xor_sync(0xffffffffu, tm, 2));
            const float mn = fmaxf(m_r[half], tm);
            const float f = __expf(m_r[half] - mn);
            float ps = 0.f;
            #pragma unroll
            for (int nt = 0; nt < 8; nt++) {
                const float p0 = __expf(sc[nt][half * 2]     - mn);
                const float p1 = __expf(sc[nt][half * 2 + 1] - mn);
                sc[nt][half * 2]     = p0;
                sc[nt][half * 2 + 1] = p1;
                ps += p0 + p1;
                acc_o[nt][half * 2]     *= f;
                acc_o[nt][half * 2 + 1] *= f;
            }
            ps += __shfl_xor_sync(0xffffffffu, ps, 1);
            ps += __shfl_xor_sync(0xffffffffu, ps, 2);
            l_r[half] = l_r[half] * f + ps;
            m_r[half] = mn;
        }

        // store next V into the spare stage
        if (kt < kmax) stsV(s ^ 1);

        // ---- O += P @ V (term-outer) ----
        #pragma unroll
        for (int ks = 0; ks < 4; ks++) {
            uint32_t ph[4], pl[4];
            const int t0 = 2 * ks, t1 = 2 * ks + 1;
            split2(sc[t0][0], sc[t0][1], ph[0], pl[0]);
            split2(sc[t0][2], sc[t0][3], ph[1], pl[1]);
            split2(sc[t1][0], sc[t1][1], ph[2], pl[2]);
            split2(sc[t1][2], sc[t1][3], ph[3], pl[3]);

            const int kb = ks * 32;
            uint32_t vh[4][4], vl[4][4];
            #pragma unroll
            for (int p = 0; p < 4; p++) {
                const uint32_t off = (uint32_t)((p * 16 + brow_q) * 144 + kb + bcb);
                LDSM_X4(vh[p][0], vh[p][1], vh[p][2], vh[p][3], uVh + off);
                LDSM_X4(vl[p][0], vl[p][1], vl[p][2], vl[p][3], uVl + off);
            }
            #pragma unroll
            for (int p = 0; p < 4; p++)
                #pragma unroll
                for (int hh = 0; hh < 2; hh++)
                    mma16816(acc_o[p * 2 + hh], ph, &vh[p][hh * 2]);
            #pragma unroll
            for (int p = 0; p < 4; p++)
                #pragma unroll
                for (int hh = 0; hh < 2; hh++)
                    mma16816(acc_o[p * 2 + hh], ph, &vl[p][hh * 2]);
            #pragma unroll
            for (int p = 0; p < 4; p++)
                #pragma unroll
                for (int hh = 0; hh < 2; hh++)
                    mma16816(acc_o[p * 2 + hh], pl, &vh[p][hh * 2]);
        }

        if (kt < kmax) {
            CP_WAIT0();
            __syncthreads();
        }
    }

    // ---- normalize + write split ctx ----
    const float inv0 = 1.0f / l_r[0];
    const float inv1 = 1.0f / l_r[1];
    const int row0 = qt * 128 + w * 16 + r0;
    #pragma unroll
    for (int nt = 0; nt < 8; nt++) {
        const int col = h * DK + nt * 8 + (lane & 3) * 2;
        uint32_t hh, ll;
        split2(acc_o[nt][0] * inv0, acc_o[nt][1] * inv0, hh, ll);
        *(uint32_t*)(Ch + ((size_t)b * SS + row0) * DD + col) = hh;
        *(uint32_t*)(Cl + ((size_t)b * SS + row0) * DD + col) = ll;
        split2(acc_o[nt][2] * inv1, acc_o[nt][3] * inv1, hh, ll);
        *(uint32_t*)(Ch + ((size_t)b * SS + row0 + 8) * DD + col) = hh;
        *(uint32_t*)(Cl + ((size_t)b * SS + row0 + 8) * DD + col) = ll;
    }
}

// ---------------------------------------------------------------------------
// out = LayerNorm(X + R) * w + b ; optional split-bf16 copy of out
// ---------------------------------------------------------------------------
template<bool SPLIT>
__global__ void __launch_bounds__(256) add_ln_kernel(
    const float* __restrict__ X, const float* __restrict__ R,
    const float* __restrict__ w, const float* __restrict__ bb,
    float* __restrict__ out,
    __nv_bfloat16* __restrict__ Oh, __nv_bfloat16* __restrict__ Ol)
{
    const int row = blockIdx.x;
    const int tid = threadIdx.x;
    const float4* x4 = (const float4*)(X + (size_t)row * DD);
    const float4* r4 = (const float4*)(R + (size_t)row * DD);
    float4 v = x4[tid];
    const float4 r = r4[tid];
    v.x += r.x; v.y += r.y; v.z += r.z; v.w += r.w;

    float sum = v.x + v.y + v.z + v.w;
    float sq  = v.x*v.x + v.y*v.y + v.z*v.z + v.w*v.w;
    #pragma unroll
    for (int off = 16; off; off >>= 1) {
        sum += __shfl_xor_sync(0xffffffffu, sum, off);
        sq  += __shfl_xor_sync(0xffffffffu, sq, off);
    }
    __shared__ float ssum[8], ssq[8];
    if ((tid & 31) == 0) { ssum[tid >> 5] = sum; ssq[tid >> 5] = sq; }
    __syncthreads();
    float tot = 0.f, totq = 0.f;
    #pragma unroll
    for (int i = 0; i < 8; i++) { tot += ssum[i]; totq += ssq[i]; }
    const float mu   = tot * (1.0f / DD);
    const float var  = totq * (1.0f / DD) - mu * mu;
    const float rstd = rsqrtf(var + 1e-5f);

    const float4 wv = ((const float4*)w)[tid];
    const float4 bv = ((const float4*)bb)[tid];
    float4 ov;
    ov.x = (v.x - mu) * rstd * wv.x + bv.x;
    ov.y = (v.y - mu) * rstd * wv.y + bv.y;
    ov.z = (v.z - mu) * rstd * wv.z + bv.z;
    ov.w = (v.w - mu) * rstd * wv.w + bv.w;
    ((float4*)(out + (size_t)row * DD))[tid] = ov;
    if (SPLIT) {
        uint32_t h0, l0, h1, l1;
        split2(ov.x, ov.y, h0, l0);
        split2(ov.z, ov.w, h1, l1);
        const size_t o = (size_t)row * DD + tid * 4;
        *(uint32_t*)(Oh + o)     = h0;  *(uint32_t*)(Oh + o + 2) = h1;
        *(uint32_t*)(Ol + o)     = l0;  *(uint32_t*)(Ol + o + 2) = l1;
    }
}

// ---------------------------------------------------------------------------
extern "C" void kernel_launch(void* const* d_in, const int* in_sizes, int n_in,
                              void* d_out, int out_size)
{
    int mi = -1;
    for (int i = 0; i < n_in; i++)
        if (in_sizes[i] == BB * SS) { mi = i; break; }

    const float *Q, *K, *V, *Wq, *Wk, *Wv, *Wo, *l1w, *l1b, *l2w, *l2b, *lnw, *lnb;
    const unsigned char* mask;
    if (mi == 3) {
        Q   = (const float*)d_in[0];  K   = (const float*)d_in[1];
        V   = (const float*)d_in[2];  mask = (const unsigned char*)d_in[3];
        Wq  = (const float*)d_in[4];  Wk  = (const float*)d_in[5];
        Wv  = (const float*)d_in[6];  Wo  = (const float*)d_in[7];
        l1w = (const float*)d_in[8];  l1b = (const float*)d_in[9];
        l2w = (const float*)d_in[10]; l2b = (const float*)d_in[11];
        lnw = (const float*)d_in[12]; lnb = (const float*)d_in[13];
    } else {
        Q   = (const float*)d_in[0];  K   = (const float*)d_in[1];
        V   = (const float*)d_in[2];
        Wq  = (const float*)d_in[3];  Wk  = (const float*)d_in[4];
        Wv  = (const float*)d_in[5];  Wo  = (const float*)d_in[6];
        l1w = (const float*)d_in[7];  l1b = (const float*)d_in[8];
        l2w = (const float*)d_in[9];  l2b = (const float*)d_in[10];
        lnw = (const float*)d_in[11]; lnb = (const float*)d_in[12];
        mask = (const unsigned char*)d_in[13];
    }

    float *gA, *gB, *gC;
    __nv_bfloat16 *bf, *wsp;
    cudaGetSymbolAddress((void**)&gA, g_A);
    cudaGetSymbolAddress((void**)&gB, g_B);
    cudaGetSymbolAddress((void**)&gC, g_C);
    cudaGetSymbolAddress((void**)&bf, g_bf);
    cudaGetSymbolAddress((void**)&wsp, g_w);

    const size_t PSZ = (size_t)MTOK * DD;
    auto P = [&](int i, int half) { return bf + ((size_t)(i * 2 + half)) * PSZ; };
    const size_t WSZ = (size_t)DD * DD;
    auto W = [&](int i, int half) { return wsp + ((size_t)(i * 2 + half)) * WSZ; };

    cudaFuncSetAttribute(mma_gemm<false, false, false, true>,
                         cudaFuncAttributeMaxDynamicSharedMemorySize, GEMM_SMEM);
    cudaFuncSetAttribute(mma_gemm<false, false, true, false>,
                         cudaFuncAttributeMaxDynamicSharedMemorySize, GEMM_SMEM);
    cudaFuncSetAttribute(mma_gemm<true, true, false, true>,
                         cudaFuncAttributeMaxDynamicSharedMemorySize, GEMM_SMEM);
    cudaFuncSetAttribute(mma_gemm<true, false, true, false>,
                         cudaFuncAttributeMaxDynamicSharedMemorySize, GEMM_SMEM);
    cudaFuncSetAttribute(attn_mma_kernel,
                         cudaFuncAttributeMaxDynamicSharedMemorySize, ATT_SMEM);

    // --- converts ---
    const dim3 wtGrid(DD / 32, DD / 32);
    conv_w_t<<<wtGrid, dim3(32, 8)>>>(Wq, W(0,0), W(0,1));
    conv_w_t<<<wtGrid, dim3(32, 8)>>>(Wk, W(1,0), W(1,1));
    conv_w_t<<<wtGrid, dim3(32, 8)>>>(Wv, W(2,0), W(2,1));
    conv_w_t<<<wtGrid, dim3(32, 8)>>>(Wo, W(3,0), W(3,1));
    conv_a<<<(int)(WSZ / 1024), 256>>>(l1w, W(4,0), W(4,1));
    conv_a<<<(int)(WSZ / 1024), 256>>>(l2w, W(5,0), W(5,1));
    conv_a<<<(int)(PSZ / 1024), 256>>>(Q, P(0,0), P(0,1));
    conv_a<<<(int)(PSZ / 1024), 256>>>(K, P(1,0), P(1,1));
    conv_a<<<(int)(PSZ / 1024), 256>>>(V, P(2,0), P(2,1));

    const dim3 gGrid(DD / 128, MTOK / 256);   // (8, 64)

    // --- QKV projections -> split outputs ---
    mma_gemm<false, false, false, true><<<gGrid, 512, GEMM_SMEM>>>(
        P(0,0), P(0,1), W(0,0), W(0,1), nullptr, nullptr, P(3,0), P(3,1));   // Qp
    mma_gemm<false, false, false, true><<<gGrid, 512, GEMM_SMEM>>>(
        P(1,0), P(1,1), W(1,0), W(1,1), nullptr, nullptr, P(0,0), P(0,1));   // Kp
    mma_gemm<false, false, false, true><<<gGrid, 512, GEMM_SMEM>>>(
        P(2,0), P(2,1), W(2,0), W(2,1), nullptr, nullptr, P(1,0), P(1,1));   // Vp

    // --- attention -> split ctx ---
    attn_mma_kernel<<<dim3(SS / 128, BB * HH), 256, ATT_SMEM>>>(
        P(3,0), P(3,1), P(0,0), P(0,1), P(1,0), P(1,1), mask, P(2,0), P(2,1));

    // --- output projection -> fp32 ---
    mma_gemm<false, false, true, false><<<gGrid, 512, GEMM_SMEM>>>(
        P(2,0), P(2,1), W(3,0), W(3,1), nullptr, gA, nullptr, nullptr);

    // --- X = LN(V_att + Q): fp32 + splits ---
    add_ln_kernel<true><<<MTOK, 256>>>(gA, Q, lnw, lnb, gB, P(3,0), P(3,1));

    // --- FFN ---
    mma_gemm<true, true, false, true><<<gGrid, 512, GEMM_SMEM>>>(
        P(3,0), P(3,1), W(4,0), W(4,1), l1b, nullptr, P(0,0), P(0,1));
    mma_gemm<true, false, true, false><<<gGrid, 512, GEMM_SMEM>>>(
        P(0,0), P(0,1), W(5,0), W(5,1), l2b, gC, nullptr, nullptr);

    // --- out = LN(ffn + X) ---
    add_ln_kernel<false><<<MTOK, 256>>>(gC, gB, lnw, lnb, (float*)d_out, nullptr, nullptr);
}